// round 9
// baseline (speedup 1.0000x reference)
#include <cuda_runtime.h>
#include <cuda_fp16.h>
#include <cstdint>
#include <cstddef>

#define D_DIM   1024
#define NBATCH  16
#define NROWS   (NBATCH * D_DIM)

#define BM 128
#define BN 128
#define BK 64
#define NSTG 2
#define NITER_FULL (D_DIM / BK)          // 16
#define NITER_HALF (NITER_FULL / 2)      // 8

#define TILE_BYTES  (BM * 128)           // 16 KB
#define STAGE_BYTES (2 * TILE_BYTES)     // 32 KB
#define SMEM_BYTES  (NSTG * STAGE_BYTES) // 64 KB

#define SLOTS      444                   // 3 CTAs/SM * 148 SMs
#define FULL_ITEMS 888                   // 2 exact waves of full tiles
#define TAIL_TILES 136                   // remaining 128x128 tiles
#define TAIL_ITEMS (2 * TAIL_TILES)      // K-split halves

// fp16 normalized-row scratch + split-K state (allocation-free)
__device__ __half g_ra[(size_t)NBATCH * D_DIM * D_DIM];
__device__ __half g_rb[(size_t)NBATCH * D_DIM * D_DIM];
__device__ float  g_part[(size_t)TAIL_TILES * BM * BN];
__device__ int    g_flag[TAIL_TILES];

// ---------------------------------------------------------------- helpers
static __device__ __forceinline__ uint32_t smem_u32(const void* p) {
    uint32_t a;
    asm("{ .reg .u64 t; cvta.to.shared.u64 t, %1; cvt.u32.u64 %0, t; }"
        : "=r"(a) : "l"(p));
    return a;
}
static __device__ __forceinline__ uint32_t sw128(uint32_t o) {
    return o ^ ((o >> 3) & 0x70u);
}
static __device__ __forceinline__ void cp16(uint32_t dst, const void* src) {
    asm volatile("cp.async.cg.shared.global [%0], [%1], 16;"
                 :: "r"(dst), "l"(src) : "memory");
}
static __device__ __forceinline__ void ldmatrix_x4(uint32_t* r, uint32_t addr) {
    asm volatile("ldmatrix.sync.aligned.m8n8.x4.shared.b16 {%0,%1,%2,%3}, [%4];"
                 : "=r"(r[0]), "=r"(r[1]), "=r"(r[2]), "=r"(r[3]) : "r"(addr));
}
static __device__ __forceinline__ void mma16816(float* d, const uint32_t* a,
                                                const uint32_t* b) {
    asm volatile(
        "mma.sync.aligned.m16n8k16.row.col.f32.f16.f16.f32 "
        "{%0,%1,%2,%3}, {%4,%5,%6,%7}, {%8,%9}, {%0,%1,%2,%3};"
        : "+f"(d[0]), "+f"(d[1]), "+f"(d[2]), "+f"(d[3])
        : "r"(a[0]), "r"(a[1]), "r"(a[2]), "r"(a[3]), "r"(b[0]), "r"(b[1]));
}

// ---------------------------------------------------------------- init
__global__ void init_kernel() {
    if (threadIdx.x < TAIL_TILES) g_flag[threadIdx.x] = 0;
}

// ---------------------------------------------------------------- normalize
__global__ void __launch_bounds__(128) norm_kernel(const float* __restrict__ a,
                                                   const float* __restrict__ b,
                                                   const float* __restrict__ w) {
    const int row = blockIdx.x;
    const float* src = (blockIdx.y == 0) ? a : b;
    __half* dst = (blockIdx.y == 0) ? g_ra : g_rb;
    const int t = threadIdx.x;

    const float4* s4 = reinterpret_cast<const float4*>(src + (size_t)row * D_DIM);
    const float4* w4 = reinterpret_cast<const float4*>(w);

    float4 x0 = s4[t];       float4 w0 = w4[t];
    float4 x1 = s4[t + 128]; float4 w1 = w4[t + 128];
    float4 v0, v1;
    v0.x = x0.x * w0.x; v0.y = x0.y * w0.y; v0.z = x0.z * w0.z; v0.w = x0.w * w0.w;
    v1.x = x1.x * w1.x; v1.y = x1.y * w1.y; v1.z = x1.z * w1.z; v1.w = x1.w * w1.w;

    float sum = v0.x * v0.x + v0.y * v0.y + v0.z * v0.z + v0.w * v0.w
              + v1.x * v1.x + v1.y * v1.y + v1.z * v1.z + v1.w * v1.w;
#pragma unroll
    for (int o = 16; o > 0; o >>= 1) sum += __shfl_xor_sync(0xFFFFFFFFu, sum, o);

    __shared__ float red[4];
    if ((t & 31) == 0) red[t >> 5] = sum;
    __syncthreads();
    float tot = red[0] + red[1] + red[2] + red[3];
    float s = rsqrtf(fmaxf(tot, 1e-12f));

    __half2* d2 = reinterpret_cast<__half2*>(dst + (size_t)row * D_DIM);
    d2[2 * t + 0]         = __floats2half2_rn(v0.x * s, v0.y * s);
    d2[2 * t + 1]         = __floats2half2_rn(v0.z * s, v0.w * s);
    d2[2 * (t + 128) + 0] = __floats2half2_rn(v1.x * s, v1.y * s);
    d2[2 * (t + 128) + 1] = __floats2half2_rn(v1.z * s, v1.w * s);
}

// ---------------------------------------------------------------- GEMM core
static __device__ __forceinline__ void load_stage(uint32_t stg,
                                                  const __half* gA, const __half* gB,
                                                  int kof, int tid) {
#pragma unroll
    for (int i = 0; i < 8; i++) {
        int q = i * 128 + tid;
        int row = q >> 3;
        int colb = (q & 7) * 16;
        uint32_t so = sw128((uint32_t)(row * 128 + colb));
        cp16(stg + so,              (const char*)(gA + (size_t)row * D_DIM + kof) + colb);
        cp16(stg + TILE_BYTES + so, (const char*)(gB + (size_t)row * D_DIM + kof) + colb);
    }
    asm volatile("cp.async.commit_group;" ::: "memory");
}

// 128x128 tile over K range [kbase, kbase + niter*BK). Warp tile 64x64.
static __device__ __forceinline__ void compute_tile(uint32_t sb,
                                                    const __half* gA,
                                                    const __half* gB,
                                                    int kbase, int niter, int tid,
                                                    float acc[4][8][4]) {
    const int wid  = tid >> 5;
    const int lane = tid & 31;
    const int wm   = wid & 1;
    const int wn   = wid >> 1;

    const int aRow  = lane & 15;
    const int aColb = (lane >> 4) << 4;
    const int bRow  = ((lane >> 4) << 3) + (lane & 7);
    const int bColb = ((lane >> 3) & 1) << 4;

    uint32_t aOff[4], bOff[4];
#pragma unroll
    for (int mt = 0; mt < 4; mt++)
        aOff[mt] = sw128((uint32_t)((wm * 64 + mt * 16 + aRow) * 128 + aColb));
#pragma unroll
    for (int nq = 0; nq < 4; nq++)
        bOff[nq] = sw128((uint32_t)((wn * 64 + nq * 16 + bRow) * 128 + bColb))
                 + TILE_BYTES;

#pragma unroll
    for (int i = 0; i < 4; i++)
#pragma unroll
        for (int j = 0; j < 8; j++)
#pragma unroll
            for (int v = 0; v < 4; v++) acc[i][j][v] = 0.0f;

    load_stage(sb + 0 * STAGE_BYTES, gA, gB, kbase + 0 * BK, tid);
    load_stage(sb + 1 * STAGE_BYTES, gA, gB, kbase + 1 * BK, tid);

    for (int it = 0; it < niter; it++) {
        // Newest committed group is chunk it+1's (or empty tail), so
        // wait_group 1 guarantees chunk it is fully resident.
        asm volatile("cp.async.wait_group 1;" ::: "memory");
        __syncthreads();

        const uint32_t sT = sb + (it & 1) * STAGE_BYTES;

#pragma unroll
        for (int kk = 0; kk < 4; kk++) {
            const uint32_t kb = kk * 32;
            uint32_t af[4][4];
#pragma unroll
            for (int mt = 0; mt < 4; mt++)
                ldmatrix_x4(af[mt], sT + (aOff[mt] ^ kb));
#pragma unroll
            for (int nq = 0; nq < 4; nq++) {
                uint32_t bf[4];
                ldmatrix_x4(bf, sT + (bOff[nq] ^ kb));
#pragma unroll
                for (int mt = 0; mt < 4; mt++) {
                    mma16816(acc[mt][2 * nq + 0], af[mt], bf + 0);
                    mma16816(acc[mt][2 * nq + 1], af[mt], bf + 2);
                }
            }
        }

        __syncthreads();                 // stage it&1 fully read by all warps
        if (it + 2 < niter)
            load_stage(sT, gA, gB, kbase + (it + 2) * BK, tid);
        else
            asm volatile("cp.async.commit_group;" ::: "memory");
    }
}

// ---------------------------------------------------------------- GEMM kernel
// Items: [0,888) full tiles (2 exact waves). [888, 888+272): K-split halves of
// the remaining 136 tiles; even item = K[0:512) -> partial + flag, odd item =
// K[512:1024) -> waits flag, adds partial, single final store.
__global__ void __launch_bounds__(128, 3) gemm_kernel(float* __restrict__ out) {
    extern __shared__ char smem[];
    const uint32_t sb = smem_u32(smem);
    const int tid  = threadIdx.x;
    const int wid  = tid >> 5;
    const int lane = tid & 31;
    const int wm   = wid & 1;
    const int wn   = wid >> 1;

    float acc[4][8][4];

#pragma unroll 1
    for (int which = 0; which < 3; which++) {
        if (which == 2 && blockIdx.x >= TAIL_ITEMS) break;
        const int item = blockIdx.x + which * SLOTS;

        int t, kbase, niter, mode, t136 = 0;
        if (item < FULL_ITEMS) {
            t = item; kbase = 0; niter = NITER_FULL; mode = 0;
        } else {
            int j = item - FULL_ITEMS;
            t136 = j >> 1;
            t = FULL_ITEMS + t136;
            kbase = (j & 1) * (D_DIM / 2);
            niter = NITER_HALF;
            mode = 1 + (j & 1);          // 1 = partial writer, 2 = finisher
        }
        const int batch = t >> 6;
        const int bm0 = ((t >> 3) & 7) * BM;
        const int bn0 = (t & 7) * BN;

        const __half* gA = g_ra + (size_t)batch * (D_DIM * D_DIM) + (size_t)bm0 * D_DIM;
        const __half* gB = g_rb + (size_t)batch * (D_DIM * D_DIM) + (size_t)bn0 * D_DIM;

        compute_tile(sb, gA, gB, kbase, niter, tid, acc);

        if (mode == 0) {
            float* oB = out + (size_t)batch * (D_DIM * D_DIM);
#pragma unroll
            for (int mt = 0; mt < 4; mt++) {
                int row = bm0 + wm * 64 + mt * 16 + (lane >> 2);
#pragma unroll
                for (int nt = 0; nt < 8; nt++) {
                    int col = bn0 + wn * 64 + nt * 8 + (lane & 3) * 2;
                    *reinterpret_cast<float2*>(oB + (size_t)row * D_DIM + col) =
                        make_float2(acc[mt][nt][0], acc[mt][nt][1]);
                    *reinterpret_cast<float2*>(oB + (size_t)(row + 8) * D_DIM + col) =
                        make_float2(acc[mt][nt][2], acc[mt][nt][3]);
                }
            }
        } else if (mode == 1) {
            float* pB = g_part + (size_t)t136 * (BM * BN);
#pragma unroll
            for (int mt = 0; mt < 4; mt++) {
                int rowl = wm * 64 + mt * 16 + (lane >> 2);
#pragma unroll
                for (int nt = 0; nt < 8; nt++) {
                    int coll = wn * 64 + nt * 8 + (lane & 3) * 2;
                    *reinterpret_cast<float2*>(pB + rowl * BN + coll) =
                        make_float2(acc[mt][nt][0], acc[mt][nt][1]);
                    *reinterpret_cast<float2*>(pB + (rowl + 8) * BN + coll) =
                        make_float2(acc[mt][nt][2], acc[mt][nt][3]);
                }
            }
            __syncthreads();
            if (tid == 0) {
                __threadfence();
                atomicExch(&g_flag[t136], 1);
            }
        } else {
            if (tid == 0) {
                while (atomicAdd(&g_flag[t136], 0) == 0) {}
                __threadfence();
            }
            __syncthreads();
            const float* pB = g_part + (size_t)t136 * (BM * BN);
            float* oB = out + (size_t)batch * (D_DIM * D_DIM);
#pragma unroll
            for (int mt = 0; mt < 4; mt++) {
                int rowl = wm * 64 + mt * 16 + (lane >> 2);
                int row = bm0 + rowl;
#pragma unroll
                for (int nt = 0; nt < 8; nt++) {
                    int coll = wn * 64 + nt * 8 + (lane & 3) * 2;
                    int col = bn0 + coll;
                    float2 p0, p1;
                    p0.x = __ldcg(pB + rowl * BN + coll);
                    p0.y = __ldcg(pB + rowl * BN + coll + 1);
                    p1.x = __ldcg(pB + (rowl + 8) * BN + coll);
                    p1.y = __ldcg(pB + (rowl + 8) * BN + coll + 1);
                    *reinterpret_cast<float2*>(oB + (size_t)row * D_DIM + col) =
                        make_float2(acc[mt][nt][0] + p0.x, acc[mt][nt][1] + p0.y);
                    *reinterpret_cast<float2*>(oB + (size_t)(row + 8) * D_DIM + col) =
                        make_float2(acc[mt][nt][2] + p1.x, acc[mt][nt][3] + p1.y);
                }
            }
        }
    }
}

// ---------------------------------------------------------------- launch
extern "C" void kernel_launch(void* const* d_in, const int* in_sizes, int n_in,
                              void* d_out, int out_size) {
    const float* a = (const float*)d_in[0];
    const float* b = (const float*)d_in[1];
    const float* w = (const float*)d_in[2];
    float* out = (float*)d_out;

    init_kernel<<<1, TAIL_TILES>>>();
    norm_kernel<<<dim3(NROWS, 2, 1), 128>>>(a, b, w);

    cudaFuncSetAttribute(gemm_kernel, cudaFuncAttributeMaxDynamicSharedMemorySize,
                         SMEM_BYTES);
    gemm_kernel<<<SLOTS, 128, SMEM_BYTES>>>(out);
}